// round 1
// baseline (speedup 1.0000x reference)
#include <cuda_runtime.h>
#include <math.h>

#define FULLMASK 0xffffffffu
#define TWO_PI_F 6.2831853071795864f

// ---------------- scratch (device globals; no allocation allowed) ----------------
__device__ float g_h1[256 * 128];
__device__ float g_h2[256 * 128];
__device__ float g_g1[256 * 256];
__device__ float g_ts[256 * 256];   // ts angles, row b: [s*64 + g]

// ---------------- sim14 single-layer op schedule (32 ops) ----------------
// OPC = control wire (-1 => RY), OPT = target wire (RY wire for RY ops)
__constant__ int c_OPC[32] = {
    -1,-1,-1,-1,-1,-1,-1,-1,
     7, 6, 5, 4, 3, 2, 1, 0,
    -1,-1,-1,-1,-1,-1,-1,-1,
     7, 0, 1, 2, 3, 4, 5, 6};
__constant__ int c_OPT[32] = {
     0, 1, 2, 3, 4, 5, 6, 7,
     0, 7, 6, 5, 4, 3, 2, 1,
     0, 1, 2, 3, 4, 5, 6, 7,
     6, 7, 0, 1, 2, 3, 4, 5};

// ---------------- helpers ----------------
__device__ __forceinline__ float g4(float4 v, int i) {
    return (i == 0) ? v.x : (i == 1) ? v.y : (i == 2) ? v.z : v.w;
}
__device__ __forceinline__ float4 splat4(float v) { return make_float4(v, v, v, v); }

// State layout: flat index n (10 bits, q0 is MSB): bits 9..5 = lane, bits 4..0 = reg r.
//   wire w in 0..4  -> lane bit (4-w)
//   wire w in 5..7  -> reg bit (9-w)   (w5->bit4/m16, w6->bit3/m8, w7->bit2/m4)
//   wire 8 (anc0)   -> reg bit 1 (m2); wire 9 (anc1) -> reg bit 0 (m1)
//   ancilla/select index s = r & 3

// RY on a lane-bit wire. cs per ancilla value (select); uniform otherwise.
__device__ __forceinline__ void ry_lane(float2 (&st)[32], int lmask, int lb, int lane,
                                        float4 c, float4 s) {
    float sg = ((lane >> lb) & 1) ? 1.f : -1.f;
    float ss0 = g4(s, 0) * sg, ss1 = g4(s, 1) * sg, ss2 = g4(s, 2) * sg, ss3 = g4(s, 3) * sg;
    float4 sv = make_float4(ss0, ss1, ss2, ss3);
#pragma unroll
    for (int r = 0; r < 32; ++r) {
        float ox = __shfl_xor_sync(FULLMASK, st[r].x, lmask);
        float oy = __shfl_xor_sync(FULLMASK, st[r].y, lmask);
        float pc = g4(c, r & 3), ps = g4(sv, r & 3);
        st[r].x = fmaf(pc, st[r].x, ps * ox);
        st[r].y = fmaf(pc, st[r].y, ps * oy);
    }
}

// RY on a reg-bit wire (mask M). For M in {16,8,4} pairs share anc (select OK);
// for M in {2,1} caller must pass uniform cs (prepare).
template <int M>
__device__ __forceinline__ void ry_reg(float2 (&st)[32], float4 c, float4 s) {
#pragma unroll
    for (int r = 0; r < 32; ++r) {
        if ((r & M) == 0) {
            const int r1 = r | M;
            float pc = g4(c, r & 3), ps = g4(s, r & 3);
            float ax = st[r].x, ay = st[r].y, bx = st[r1].x, by = st[r1].y;
            st[r].x = fmaf(pc, ax, -ps * bx);
            st[r].y = fmaf(pc, ay, -ps * by);
            st[r1].x = fmaf(ps, ax, pc * bx);
            st[r1].y = fmaf(ps, ay, pc * by);
        }
    }
}

// CRX with target on a lane-bit wire. out = c*mine - i*s*other (both sides), if control==1.
__device__ __forceinline__ void crx_lane(float2 (&st)[32], int tmask,
                                         bool claneCtrl, int cLaneBit, int cRegMask,
                                         int lane, float4 c, float4 s) {
    bool lact = claneCtrl ? (((lane >> cLaneBit) & 1) != 0) : true;
#pragma unroll
    for (int r = 0; r < 32; ++r) {
        float ox = __shfl_xor_sync(FULLMASK, st[r].x, tmask);
        float oy = __shfl_xor_sync(FULLMASK, st[r].y, tmask);
        bool act = claneCtrl ? lact : ((r & cRegMask) != 0);
        float pc = g4(c, r & 3), ps = g4(s, r & 3);
        float nx = fmaf(pc, st[r].x, ps * oy);
        float ny = fmaf(pc, st[r].y, -ps * ox);
        if (act) { st[r].x = nx; st[r].y = ny; }
    }
}

// CRX with target on a reg-bit wire (mask M).
template <int M>
__device__ __forceinline__ void crx_reg(float2 (&st)[32],
                                        bool claneCtrl, int cLaneBit, int cRegMask,
                                        int lane, float4 c, float4 s) {
    bool lact = claneCtrl ? (((lane >> cLaneBit) & 1) != 0) : true;
#pragma unroll
    for (int r = 0; r < 32; ++r) {
        if ((r & M) == 0) {
            const int r1 = r | M;
            bool act = claneCtrl ? lact : ((r & cRegMask) != 0);
            float pc = g4(c, r & 3), ps = g4(s, r & 3);
            float ax = st[r].x, ay = st[r].y, bx = st[r1].x, by = st[r1].y;
            float n0x = fmaf(pc, ax, ps * by);
            float n0y = fmaf(pc, ay, -ps * bx);
            float n1x = fmaf(pc, bx, ps * ay);
            float n1y = fmaf(pc, by, -ps * ax);
            if (act) { st[r] = make_float2(n0x, n0y); st[r1] = make_float2(n1x, n1y); }
        }
    }
}

// RZ on a reg-bit wire (ancilla only). amp *= exp(-i th/2) if bit==0 else exp(+i th/2)
template <int M>
__device__ __forceinline__ void rz_reg(float2 (&st)[32], float c, float s) {
#pragma unroll
    for (int r = 0; r < 32; ++r) {
        float ss = (r & M) ? s : -s;
        float x = st[r].x, y = st[r].y;
        st[r].x = fmaf(c, x, -ss * y);
        st[r].y = fmaf(c, y, ss * x);
    }
}

// CNOT(control=wire8 (bit1), target=wire9 (bit0))
__device__ __forceinline__ void cnot_st(float2 (&st)[32]) {
#pragma unroll
    for (int r = 0; r < 32; ++r) {
        if ((r & 3) == 2) { float2 tmp = st[r]; st[r] = st[r | 1]; st[r | 1] = tmp; }
    }
}

// pcphase: * exp(+i phi) if anc==0 else exp(-i phi)
__device__ __forceinline__ void pcphase_g(float2 (&st)[32], float cphi, float sphi) {
#pragma unroll
    for (int r = 0; r < 32; ++r) {
        float ss = ((r & 3) == 0) ? sphi : -sphi;
        float x = st[r].x, y = st[r].y;
        st[r].x = fmaf(cphi, x, -ss * y);
        st[r].y = fmaf(cphi, y, ss * x);
    }
}

__device__ __forceinline__ void apply_sim_op(float2 (&st)[32], int lane,
                                             int cwire, int twire, float4 c, float4 s) {
    if (cwire < 0) {  // RY on wire twire
        int w = twire;
        if (w < 5)      ry_lane(st, 1 << (4 - w), 4 - w, lane, c, s);
        else if (w == 5) ry_reg<16>(st, c, s);
        else if (w == 6) ry_reg<8>(st, c, s);
        else             ry_reg<4>(st, c, s);
    } else {            // CRX(control=cwire, target=twire)
        bool cl = (cwire < 5);
        int clb = cl ? (4 - cwire) : 0;
        int crm = cl ? 0 : (1 << (9 - cwire));
        int tw = twire;
        if (tw < 5)      crx_lane(st, 1 << (4 - tw), cl, clb, crm, lane, c, s);
        else if (tw == 5) crx_reg<16>(st, cl, clb, crm, lane, c, s);
        else if (tw == 6) crx_reg<8>(st, cl, clb, crm, lane, c, s);
        else              crx_reg<4>(st, cl, clb, crm, lane, c, s);
    }
}

// sim14 with 2 layers, theta per-ancilla from tab[step*4 + s] = (cos(th/2), sin(th/2))
__device__ __forceinline__ void run_sim14_2l(float2 (&st)[32], int lane,
                                             const float2* tab, bool adj) {
    if (!adj) {
#pragma unroll 1
        for (int step = 0; step < 64; ++step) {
            int o = step & 31;
            float2 t0 = tab[step * 4 + 0], t1 = tab[step * 4 + 1];
            float2 t2 = tab[step * 4 + 2], t3 = tab[step * 4 + 3];
            float4 c = make_float4(t0.x, t1.x, t2.x, t3.x);
            float4 s = make_float4(t0.y, t1.y, t2.y, t3.y);
            apply_sim_op(st, lane, c_OPC[o], c_OPT[o], c, s);
        }
    } else {
#pragma unroll 1
        for (int step = 63; step >= 0; --step) {
            int o = step & 31;
            float2 t0 = tab[step * 4 + 0], t1 = tab[step * 4 + 1];
            float2 t2 = tab[step * 4 + 2], t3 = tab[step * 4 + 3];
            float4 c = make_float4(t0.x, t1.x, t2.x, t3.x);
            float4 s = make_float4(-t0.y, -t1.y, -t2.y, -t3.y);
            apply_sim_op(st, lane, c_OPC[o], c_OPT[o], c, s);
        }
    }
}

// prepare: tabp[ly*4 + qi*2 + c] = (cos(p/2), sin(p/2)); wire 8+qi
__device__ __forceinline__ void do_prepare(float2 (&st)[32], const float2* tabp, bool adj) {
    if (!adj) {
#pragma unroll
        for (int ly = 0; ly < 2; ++ly) {
            float2 a = tabp[ly * 4 + 0]; ry_reg<2>(st, splat4(a.x), splat4(a.y));
            float2 z = tabp[ly * 4 + 1]; rz_reg<2>(st, z.x, z.y);
            float2 a2 = tabp[ly * 4 + 2]; ry_reg<1>(st, splat4(a2.x), splat4(a2.y));
            float2 z2 = tabp[ly * 4 + 3]; rz_reg<1>(st, z2.x, z2.y);
            cnot_st(st);
        }
    } else {
#pragma unroll
        for (int ly = 1; ly >= 0; --ly) {
            cnot_st(st);
            float2 z2 = tabp[ly * 4 + 3]; rz_reg<1>(st, z2.x, -z2.y);
            float2 a2 = tabp[ly * 4 + 2]; ry_reg<1>(st, splat4(a2.x), splat4(-a2.y));
            float2 z = tabp[ly * 4 + 1]; rz_reg<2>(st, z.x, -z.y);
            float2 a = tabp[ly * 4 + 0]; ry_reg<2>(st, splat4(a.x), splat4(-a.y));
        }
    }
}

// ---------------- simulate kernel: one warp per batch element ----------------
__global__ void __launch_bounds__(32) k_sim(
    const float* __restrict__ prep_p, const float* __restrict__ sig,
    const float* __restrict__ qff,
    const float* __restrict__ A_obs, const float* __restrict__ B_obs,
    const float* __restrict__ D_obs,
    const float* __restrict__ head_w, const float* __restrict__ head_b,
    float* __restrict__ out) {
    __shared__ float2 tabsel[256];  // [g*4 + s]
    __shared__ float2 tabq[32];
    __shared__ float2 tabp[8];
    __shared__ float2 tabsig[4];
    __shared__ float2 sstate[1024];
    __shared__ float ebuf[7];

    const int lane = threadIdx.x;
    const int b = blockIdx.x;
    const float* tsr = g_ts + b * 256;

    for (int i = lane; i < 256; i += 32) {
        int s = i >> 6, g = i & 63;
        float sn, cc; sincosf(tsr[i] * 0.5f, &sn, &cc);
        tabsel[g * 4 + s] = make_float2(cc, sn);
    }
    { float sn, cc; sincosf(qff[lane] * 0.5f, &sn, &cc); tabq[lane] = make_float2(cc, sn); }
    if (lane < 8) { float sn, cc; sincosf(prep_p[lane] * 0.5f, &sn, &cc); tabp[lane] = make_float2(cc, sn); }
    if (lane < 4) { float sn, cc; sincosf(sig[lane], &sn, &cc); tabsig[lane] = make_float2(cc, sn); }
    __syncwarp();

    float2 st[32];
#pragma unroll
    for (int r = 0; r < 32; ++r) st[r] = make_float2(0.f, 0.f);
    if (lane == 0) st[0].x = 1.f;

    { float2 p = tabsig[0]; pcphase_g(st, p.x, p.y); }
#pragma unroll 1
    for (int k = 0; k < 3; ++k) {
        do_prepare(st, tabp, false);
        run_sim14_2l(st, lane, tabsel, (k & 1) != 0);
        do_prepare(st, tabp, true);
        float2 p = tabsig[k + 1];
        pcphase_g(st, p.x, p.y);
    }
    // final sim14 with qff params, 1 layer, uniform theta
#pragma unroll 1
    for (int step = 0; step < 32; ++step) {
        float2 tq = tabq[step];
        apply_sim_op(st, lane, c_OPC[step], c_OPT[step], splat4(tq.x), splat4(tq.y));
    }

    // dump state to shared for expectation values
#pragma unroll
    for (int r = 0; r < 32; ++r) sstate[(lane << 5) | r] = st[r];
    __syncwarp();

#pragma unroll 1
    for (int w = 0; w < 7; ++w) {
        const float* Aw = A_obs + w * 6;
        const float* Bw = B_obs + w * 6;
        const float* Dw = D_obs + w * 4;
        float d0 = 2.f * Dw[1], d1 = 2.f * Dw[2], d2 = 2.f * Dw[3];
        float a10 = Aw[0], b10 = Bw[0], a20 = Aw[1], b20 = Bw[1], a21 = Aw[2], b21 = Bw[2];
        float a30 = Aw[3], b30 = Bw[3], a31 = Aw[4], b31 = Bw[4], a32 = Aw[5], b32 = Bw[5];
        int b1 = 8 - w;
        int m1 = 1 << b1, m0 = m1 << 1;
        int lowmask = m1 - 1;
        float acc = 0.f;
        for (int gi = lane; gi < 256; gi += 32) {
            int n = ((gi & ~lowmask) << 2) | (gi & lowmask);
            float2 v0 = sstate[n];
            float2 v1 = sstate[n + m1];
            float2 v2 = sstate[n + m0];
            float2 v3 = sstate[n + m0 + m1];
            acc += d0 * (v0.x * v0.x + v0.y * v0.y);
            acc += d1 * (v1.x * v1.x + v1.y * v1.y);
            acc += d2 * (v2.x * v2.x + v2.y * v2.y);
#define CROSS(vi, vj, aa, bb) { \
            float pr = vi.x * vj.x + vi.y * vj.y; \
            float pim = vi.x * vj.y - vi.y * vj.x; \
            acc += 2.f * (pr * (aa) - pim * (bb)); }
            CROSS(v1, v0, a10, b10)
            CROSS(v2, v0, a20, b20)
            CROSS(v2, v1, a21, b21)
            CROSS(v3, v0, a30, b30)
            CROSS(v3, v1, a31, b31)
            CROSS(v3, v2, a32, b32)
#undef CROSS
        }
#pragma unroll
        for (int off = 16; off; off >>= 1) acc += __shfl_xor_sync(FULLMASK, acc, off);
        if (lane == 0) ebuf[w] = acc;
    }
    __syncwarp();

    // head: out[b][j] = sum_w e[w] * head_w[j*7+w] + head_b[j]
#pragma unroll
    for (int u = 0; u < 4; ++u) {
        int j = u * 32 + lane;
        float o = head_b[j];
#pragma unroll
        for (int w = 0; w < 7; ++w) o = fmaf(ebuf[w], head_w[j * 7 + w], o);
        out[b * 128 + j] = o;
    }
}

// ---------------- MLP kernels (row-tiled, 8 rows/block) ----------------
__global__ void k_te1(const float* __restrict__ t,
                      const float* __restrict__ w,
                      const float* __restrict__ bv) {
    __shared__ float xs[8][128];
    int r0 = blockIdx.x * 8;
    int tid = threadIdx.x;
    for (int idx = tid; idx < 8 * 128; idx += 128) {
        int row = idx >> 7, i = idx & 127;
        float tv = t[r0 + row];
        int ii = (i < 64) ? i : (i - 64);
        float f = expf(-9.2103403719761836f * (float)ii * (1.f / 64.f));
        float a = tv * f;
        xs[row][i] = (i < 64) ? cosf(a) : sinf(a);
    }
    __syncthreads();
    int j = tid;
    float acc[8];
    float bj = bv[j];
#pragma unroll
    for (int r = 0; r < 8; ++r) acc[r] = bj;
    const float4* w4 = reinterpret_cast<const float4*>(w + j * 128);
    for (int k4 = 0; k4 < 32; ++k4) {
        float4 wv = w4[k4];
#pragma unroll
        for (int r = 0; r < 8; ++r) {
            float4 xv = *reinterpret_cast<const float4*>(&xs[r][k4 * 4]);
            acc[r] = fmaf(xv.x, wv.x, acc[r]);
            acc[r] = fmaf(xv.y, wv.y, acc[r]);
            acc[r] = fmaf(xv.z, wv.z, acc[r]);
            acc[r] = fmaf(xv.w, wv.w, acc[r]);
        }
    }
#pragma unroll
    for (int r = 0; r < 8; ++r) {
        float x = acc[r];
        g_h1[(r0 + r) * 128 + j] = x * (1.f / (1.f + expf(-x)));  // silu
    }
}

__global__ void k_te2(const float* __restrict__ w, const float* __restrict__ bv) {
    __shared__ float xs[8][128];
    int r0 = blockIdx.x * 8;
    int tid = threadIdx.x;
    for (int idx = tid; idx < 8 * 128; idx += 128) {
        int row = idx >> 7, i = idx & 127;
        xs[row][i] = g_h1[(r0 + row) * 128 + i];
    }
    __syncthreads();
    int j = tid;
    float acc[8];
    float bj = bv[j];
#pragma unroll
    for (int r = 0; r < 8; ++r) acc[r] = bj;
    const float4* w4 = reinterpret_cast<const float4*>(w + j * 128);
    for (int k4 = 0; k4 < 32; ++k4) {
        float4 wv = w4[k4];
#pragma unroll
        for (int r = 0; r < 8; ++r) {
            float4 xv = *reinterpret_cast<const float4*>(&xs[r][k4 * 4]);
            acc[r] = fmaf(xv.x, wv.x, acc[r]);
            acc[r] = fmaf(xv.y, wv.y, acc[r]);
            acc[r] = fmaf(xv.z, wv.z, acc[r]);
            acc[r] = fmaf(xv.w, wv.w, acc[r]);
        }
    }
#pragma unroll
    for (int r = 0; r < 8; ++r) g_h2[(r0 + r) * 128 + j] = acc[r];
}

__global__ void k_ip1(const float* __restrict__ z_t,
                      const float* __restrict__ w, const float* __restrict__ bv) {
    __shared__ float xs[8][256];
    int r0 = blockIdx.x * 8;
    int tid = threadIdx.x;
    for (int idx = tid; idx < 8 * 256; idx += 256) {
        int row = idx >> 8, kk = idx & 255;
        xs[row][kk] = (kk < 128) ? z_t[(r0 + row) * 128 + kk]
                                 : g_h2[(r0 + row) * 128 + (kk - 128)];
    }
    __syncthreads();
    int j = tid;
    float acc[8];
    float bj = bv[j];
#pragma unroll
    for (int r = 0; r < 8; ++r) acc[r] = bj;
    const float4* w4 = reinterpret_cast<const float4*>(w + j * 256);
    for (int k4 = 0; k4 < 64; ++k4) {
        float4 wv = w4[k4];
#pragma unroll
        for (int r = 0; r < 8; ++r) {
            float4 xv = *reinterpret_cast<const float4*>(&xs[r][k4 * 4]);
            acc[r] = fmaf(xv.x, wv.x, acc[r]);
            acc[r] = fmaf(xv.y, wv.y, acc[r]);
            acc[r] = fmaf(xv.z, wv.z, acc[r]);
            acc[r] = fmaf(xv.w, wv.w, acc[r]);
        }
    }
#pragma unroll
    for (int r = 0; r < 8; ++r) {
        float x = acc[r];
        g_g1[(r0 + r) * 256 + j] = x * (1.f / (1.f + expf(-x)));  // silu
    }
}

__global__ void k_ip2(const float* __restrict__ w, const float* __restrict__ bv) {
    __shared__ float xs[8][256];
    int r0 = blockIdx.x * 8;
    int tid = threadIdx.x;
    for (int idx = tid; idx < 8 * 256; idx += 256) {
        int row = idx >> 8, kk = idx & 255;
        xs[row][kk] = g_g1[(r0 + row) * 256 + kk];
    }
    __syncthreads();
    int j = tid;
    float acc[8];
    float bj = bv[j];
#pragma unroll
    for (int r = 0; r < 8; ++r) acc[r] = bj;
    const float4* w4 = reinterpret_cast<const float4*>(w + j * 256);
    for (int k4 = 0; k4 < 64; ++k4) {
        float4 wv = w4[k4];
#pragma unroll
        for (int r = 0; r < 8; ++r) {
            float4 xv = *reinterpret_cast<const float4*>(&xs[r][k4 * 4]);
            acc[r] = fmaf(xv.x, wv.x, acc[r]);
            acc[r] = fmaf(xv.y, wv.y, acc[r]);
            acc[r] = fmaf(xv.z, wv.z, acc[r]);
            acc[r] = fmaf(xv.w, wv.w, acc[r]);
        }
    }
#pragma unroll
    for (int r = 0; r < 8; ++r) {
        float x = acc[r];
        float sg = 1.f / (1.f + expf(-x));
        g_ts[(r0 + r) * 256 + j] = sg * TWO_PI_F;
    }
}

// ---------------- launch ----------------
extern "C" void kernel_launch(void* const* d_in, const int* in_sizes, int n_in,
                              void* d_out, int out_size) {
    const float* z_t    = (const float*)d_in[0];
    const float* t      = (const float*)d_in[1];
    const float* te_w1  = (const float*)d_in[2];
    const float* te_b1  = (const float*)d_in[3];
    const float* te_w2  = (const float*)d_in[4];
    const float* te_b2  = (const float*)d_in[5];
    const float* ip_w1  = (const float*)d_in[6];
    const float* ip_b1  = (const float*)d_in[7];
    const float* ip_w2  = (const float*)d_in[8];
    const float* ip_b2  = (const float*)d_in[9];
    const float* prep   = (const float*)d_in[10];
    const float* sig    = (const float*)d_in[11];
    const float* qff    = (const float*)d_in[12];
    const float* A_obs  = (const float*)d_in[13];
    const float* B_obs  = (const float*)d_in[14];
    const float* D_obs  = (const float*)d_in[15];
    const float* head_w = (const float*)d_in[16];
    const float* head_b = (const float*)d_in[17];
    float* out = (float*)d_out;

    k_te1<<<32, 128>>>(t, te_w1, te_b1);
    k_te2<<<32, 128>>>(te_w2, te_b2);
    k_ip1<<<32, 256>>>(z_t, ip_w1, ip_b1);
    k_ip2<<<32, 256>>>(ip_w2, ip_b2);
    k_sim<<<256, 32>>>(prep, sig, qff, A_obs, B_obs, D_obs, head_w, head_b, out);
}

// round 2
// speedup vs baseline: 1.8280x; 1.8280x over previous
#include <cuda_runtime.h>
#include <math.h>

#define FULLMASK 0xffffffffu
#define TWO_PI_F 6.2831853071795864f

// ---------------- scratch ----------------
__device__ float g_ts[256 * 256];   // ts angles, row b: [s*64 + g]

// ---------------- sim14 single-layer op schedule (32 ops) ----------------
__constant__ int c_OPC[32] = {
    -1,-1,-1,-1,-1,-1,-1,-1,
     7, 6, 5, 4, 3, 2, 1, 0,
    -1,-1,-1,-1,-1,-1,-1,-1,
     7, 0, 1, 2, 3, 4, 5, 6};
__constant__ int c_OPT[32] = {
     0, 1, 2, 3, 4, 5, 6, 7,
     0, 7, 6, 5, 4, 3, 2, 1,
     0, 1, 2, 3, 4, 5, 6, 7,
     6, 7, 0, 1, 2, 3, 4, 5};

// ---------------- helpers ----------------
__device__ __forceinline__ float g4(float4 v, int i) {
    return (i == 0) ? v.x : (i == 1) ? v.y : (i == 2) ? v.z : v.w;
}
__device__ __forceinline__ float4 splat4(float v) { return make_float4(v, v, v, v); }

// State layout (2 warps per batch element, 64 threads):
//   flat index n (10 bits): bit9=w0 ... bit5=w4 (lane bits 4..0),
//   bit4=w5 (WARP bit), bit3=w6, bit2=w7, bit1=w8(anc0), bit0=w9(anc1).
//   Each thread holds 16 float2: r = bits 3..0. select index s = r & 3.
#define OIDX(n) ((n) ^ (((n) >> 5) & 31))

// RY on a lane-bit wire
__device__ __forceinline__ void ry_lane(float2 (&st)[16], int lmask, int lb, int lane,
                                        float4 c, float4 s) {
    float sg = ((lane >> lb) & 1) ? 1.f : -1.f;
    float4 sv = make_float4(g4(s,0)*sg, g4(s,1)*sg, g4(s,2)*sg, g4(s,3)*sg);
#pragma unroll
    for (int r = 0; r < 16; ++r) {
        float ox = __shfl_xor_sync(FULLMASK, st[r].x, lmask);
        float oy = __shfl_xor_sync(FULLMASK, st[r].y, lmask);
        float pc = g4(c, r & 3), ps = g4(sv, r & 3);
        st[r].x = fmaf(pc, st[r].x, ps * ox);
        st[r].y = fmaf(pc, st[r].y, ps * oy);
    }
}

// RY on a reg-bit wire (mask M in {8,4,2,1})
template <int M>
__device__ __forceinline__ void ry_reg(float2 (&st)[16], float4 c, float4 s) {
#pragma unroll
    for (int r = 0; r < 16; ++r) {
        if ((r & M) == 0) {
            const int r1 = r | M;
            float pc = g4(c, r & 3), ps = g4(s, r & 3);
            float ax = st[r].x, ay = st[r].y, bx = st[r1].x, by = st[r1].y;
            st[r].x = fmaf(pc, ax, -ps * bx);
            st[r].y = fmaf(pc, ay, -ps * by);
            st[r1].x = fmaf(ps, ax, pc * bx);
            st[r1].y = fmaf(ps, ay, pc * by);
        }
    }
}

// CRX with target on a lane-bit wire. act = actBase && (crm==0 || (r&crm))
__device__ __forceinline__ void crx_lane(float2 (&st)[16], int tmask,
                                         bool actBase, int crm,
                                         float4 c, float4 s) {
#pragma unroll
    for (int r = 0; r < 16; ++r) {
        float ox = __shfl_xor_sync(FULLMASK, st[r].x, tmask);
        float oy = __shfl_xor_sync(FULLMASK, st[r].y, tmask);
        bool act = actBase && (crm == 0 || (r & crm) != 0);
        float pc = g4(c, r & 3), ps = g4(s, r & 3);
        float nx = fmaf(pc, st[r].x, ps * oy);
        float ny = fmaf(pc, st[r].y, -ps * ox);
        if (act) { st[r].x = nx; st[r].y = ny; }
    }
}

// CRX with target on a reg-bit wire (mask M)
template <int M>
__device__ __forceinline__ void crx_reg(float2 (&st)[16], bool actBase, int crm,
                                        float4 c, float4 s) {
#pragma unroll
    for (int r = 0; r < 16; ++r) {
        if ((r & M) == 0) {
            const int r1 = r | M;
            bool act = actBase && (crm == 0 || (r & crm) != 0);
            float pc = g4(c, r & 3), ps = g4(s, r & 3);
            float ax = st[r].x, ay = st[r].y, bx = st[r1].x, by = st[r1].y;
            float n0x = fmaf(pc, ax, ps * by);
            float n0y = fmaf(pc, ay, -ps * bx);
            float n1x = fmaf(pc, bx, ps * ay);
            float n1y = fmaf(pc, by, -ps * ax);
            if (act) { st[r] = make_float2(n0x, n0y); st[r1] = make_float2(n1x, n1y); }
        }
    }
}

// Op (RY or CRX) whose target is wire 5 (the warp bit): smem exchange.
__device__ __forceinline__ void wire5_op(float2 (&st)[16], float* sx, float* sy,
                                         int tid, int W, bool isRY,
                                         bool actBase, int crm,
                                         float4 c, float4 s) {
    __syncthreads();
#pragma unroll
    for (int r = 0; r < 16; ++r) { sx[r * 64 + tid] = st[r].x; sy[r * 64 + tid] = st[r].y; }
    __syncthreads();
    const int p = tid ^ 32;
#pragma unroll
    for (int r = 0; r < 16; ++r) {
        float ox = sx[r * 64 + p], oy = sy[r * 64 + p];
        float pc = g4(c, r & 3), ps = g4(s, r & 3);
        if (isRY) {
            float sg = W ? ps : -ps;
            st[r].x = fmaf(pc, st[r].x, sg * ox);
            st[r].y = fmaf(pc, st[r].y, sg * oy);
        } else {
            bool act = actBase && (crm == 0 || (r & crm) != 0);
            float nx = fmaf(pc, st[r].x, ps * oy);
            float ny = fmaf(pc, st[r].y, -ps * ox);
            if (act) { st[r].x = nx; st[r].y = ny; }
        }
    }
}

// RZ on a reg-bit wire (ancilla)
template <int M>
__device__ __forceinline__ void rz_reg(float2 (&st)[16], float c, float s) {
#pragma unroll
    for (int r = 0; r < 16; ++r) {
        float ss = (r & M) ? s : -s;
        float x = st[r].x, y = st[r].y;
        st[r].x = fmaf(c, x, -ss * y);
        st[r].y = fmaf(c, y, ss * x);
    }
}

__device__ __forceinline__ void cnot_st(float2 (&st)[16]) {
#pragma unroll
    for (int r = 0; r < 16; ++r) {
        if ((r & 3) == 2) { float2 tmp = st[r]; st[r] = st[r | 1]; st[r | 1] = tmp; }
    }
}

__device__ __forceinline__ void pcphase_g(float2 (&st)[16], float cphi, float sphi) {
#pragma unroll
    for (int r = 0; r < 16; ++r) {
        float ss = ((r & 3) == 0) ? sphi : -sphi;
        float x = st[r].x, y = st[r].y;
        st[r].x = fmaf(cphi, x, -ss * y);
        st[r].y = fmaf(cphi, y, ss * x);
    }
}

__device__ __forceinline__ void apply_op(float2 (&st)[16], int lane, int W, int tid,
                                         float* sx, float* sy,
                                         int cw, int tw, float4 c, float4 s) {
    if (cw < 0) {  // RY
        if (tw < 5)       ry_lane(st, 1 << (4 - tw), 4 - tw, lane, c, s);
        else if (tw == 5) wire5_op(st, sx, sy, tid, W, true, true, 0, c, s);
        else if (tw == 6) ry_reg<8>(st, c, s);
        else              ry_reg<4>(st, c, s);
    } else {       // CRX
        bool actBase; int crm = 0;
        if (cw < 5)       actBase = ((lane >> (4 - cw)) & 1) != 0;
        else if (cw == 5) actBase = (W == 1);
        else { actBase = true; crm = (cw == 6) ? 8 : 4; }
        if (tw < 5)       crx_lane(st, 1 << (4 - tw), actBase, crm, c, s);
        else if (tw == 5) wire5_op(st, sx, sy, tid, W, false, actBase, crm, c, s);
        else if (tw == 6) crx_reg<8>(st, actBase, crm, c, s);
        else              crx_reg<4>(st, actBase, crm, c, s);
    }
}

__device__ __forceinline__ void run_sim14_2l(float2 (&st)[16], int lane, int W, int tid,
                                             float* sx, float* sy,
                                             const float2* tab, bool adj) {
    if (!adj) {
#pragma unroll 1
        for (int step = 0; step < 64; ++step) {
            int o = step & 31;
            float2 t0 = tab[step*4+0], t1 = tab[step*4+1], t2 = tab[step*4+2], t3 = tab[step*4+3];
            float4 c = make_float4(t0.x, t1.x, t2.x, t3.x);
            float4 s = make_float4(t0.y, t1.y, t2.y, t3.y);
            apply_op(st, lane, W, tid, sx, sy, c_OPC[o], c_OPT[o], c, s);
        }
    } else {
#pragma unroll 1
        for (int step = 63; step >= 0; --step) {
            int o = step & 31;
            float2 t0 = tab[step*4+0], t1 = tab[step*4+1], t2 = tab[step*4+2], t3 = tab[step*4+3];
            float4 c = make_float4(t0.x, t1.x, t2.x, t3.x);
            float4 s = make_float4(-t0.y, -t1.y, -t2.y, -t3.y);
            apply_op(st, lane, W, tid, sx, sy, c_OPC[o], c_OPT[o], c, s);
        }
    }
}

__device__ __forceinline__ void do_prepare(float2 (&st)[16], const float2* tabp, bool adj) {
    if (!adj) {
#pragma unroll
        for (int ly = 0; ly < 2; ++ly) {
            float2 a  = tabp[ly*4+0]; ry_reg<2>(st, splat4(a.x),  splat4(a.y));
            float2 z  = tabp[ly*4+1]; rz_reg<2>(st, z.x, z.y);
            float2 a2 = tabp[ly*4+2]; ry_reg<1>(st, splat4(a2.x), splat4(a2.y));
            float2 z2 = tabp[ly*4+3]; rz_reg<1>(st, z2.x, z2.y);
            cnot_st(st);
        }
    } else {
#pragma unroll
        for (int ly = 1; ly >= 0; --ly) {
            cnot_st(st);
            float2 z2 = tabp[ly*4+3]; rz_reg<1>(st, z2.x, -z2.y);
            float2 a2 = tabp[ly*4+2]; ry_reg<1>(st, splat4(a2.x), splat4(-a2.y));
            float2 z  = tabp[ly*4+1]; rz_reg<2>(st, z.x, -z.y);
            float2 a  = tabp[ly*4+0]; ry_reg<2>(st, splat4(a.x),  splat4(-a.y));
        }
    }
}

// ---------------- simulate kernel: 2 warps per batch element ----------------
__global__ void __launch_bounds__(64) k_sim(
    const float* __restrict__ prep_p, const float* __restrict__ sig,
    const float* __restrict__ qff,
    const float* __restrict__ A_obs, const float* __restrict__ B_obs,
    const float* __restrict__ D_obs,
    const float* __restrict__ head_w, const float* __restrict__ head_b,
    float* __restrict__ out) {
    __shared__ float sx[1024];      // exchange / obs real
    __shared__ float sy[1024];      // exchange / obs imag
    __shared__ float2 tabsel[256];  // [g*4 + s]
    __shared__ float2 tabq[32];
    __shared__ float2 tabp[8];
    __shared__ float2 tabsig[4];
    __shared__ float part[14];

    const int tid  = threadIdx.x;
    const int lane = tid & 31;
    const int W    = tid >> 5;
    const int b    = blockIdx.x;
    const float* tsr = g_ts + b * 256;

    for (int i = tid; i < 256; i += 64) {
        int s = i >> 6, g = i & 63;
        float sn, cc; sincosf(tsr[i] * 0.5f, &sn, &cc);
        tabsel[g * 4 + s] = make_float2(cc, sn);
    }
    if (tid < 32) { float sn, cc; sincosf(qff[tid] * 0.5f, &sn, &cc); tabq[tid] = make_float2(cc, sn); }
    if (tid < 8)  { float sn, cc; sincosf(prep_p[tid] * 0.5f, &sn, &cc); tabp[tid] = make_float2(cc, sn); }
    if (tid < 4)  { float sn, cc; sincosf(sig[tid], &sn, &cc); tabsig[tid] = make_float2(cc, sn); }
    __syncthreads();

    float2 st[16];
#pragma unroll
    for (int r = 0; r < 16; ++r) st[r] = make_float2(0.f, 0.f);
    if (tid == 0) st[0].x = 1.f;

    { float2 p = tabsig[0]; pcphase_g(st, p.x, p.y); }
#pragma unroll 1
    for (int k = 0; k < 3; ++k) {
        do_prepare(st, tabp, false);
        run_sim14_2l(st, lane, W, tid, sx, sy, tabsel, (k & 1) != 0);
        do_prepare(st, tabp, true);
        float2 p = tabsig[k + 1];
        pcphase_g(st, p.x, p.y);
    }
    // final sim14 with qff params, 1 layer
#pragma unroll 1
    for (int step = 0; step < 32; ++step) {
        float2 tq = tabq[step];
        apply_op(st, lane, W, tid, sx, sy, c_OPC[step], c_OPT[step],
                 splat4(tq.x), splat4(tq.y));
    }

    // dump state to shared (swizzled) for expectation values
    __syncthreads();
#pragma unroll
    for (int r = 0; r < 16; ++r) {
        int n = (lane << 5) | (W << 4) | r;
        sx[OIDX(n)] = st[r].x; sy[OIDX(n)] = st[r].y;
    }
    __syncthreads();

#pragma unroll 1
    for (int w = 0; w < 7; ++w) {
        const float* Aw = A_obs + w * 6;
        const float* Bw = B_obs + w * 6;
        const float* Dw = D_obs + w * 4;
        float d0 = 2.f * Dw[1], d1 = 2.f * Dw[2], d2 = 2.f * Dw[3];
        float a10 = Aw[0], b10 = Bw[0], a20 = Aw[1], b20 = Bw[1], a21 = Aw[2], b21 = Bw[2];
        float a30 = Aw[3], b30 = Bw[3], a31 = Aw[4], b31 = Bw[4], a32 = Aw[5], b32 = Bw[5];
        int b1 = 8 - w;
        int m1 = 1 << b1, m0 = m1 << 1;
        int lowmask = m1 - 1;
        float acc = 0.f;
        for (int gi = tid; gi < 256; gi += 64) {
            int n = ((gi & ~lowmask) << 2) | (gi & lowmask);
            int i0 = OIDX(n), i1 = OIDX(n + m1), i2 = OIDX(n + m0), i3 = OIDX(n + m0 + m1);
            float2 v0 = make_float2(sx[i0], sy[i0]);
            float2 v1 = make_float2(sx[i1], sy[i1]);
            float2 v2 = make_float2(sx[i2], sy[i2]);
            float2 v3 = make_float2(sx[i3], sy[i3]);
            acc += d0 * (v0.x * v0.x + v0.y * v0.y);
            acc += d1 * (v1.x * v1.x + v1.y * v1.y);
            acc += d2 * (v2.x * v2.x + v2.y * v2.y);
#define CROSS(vi, vj, aa, bb) { \
            float pr = vi.x * vj.x + vi.y * vj.y; \
            float pim = vi.x * vj.y - vi.y * vj.x; \
            acc += 2.f * (pr * (aa) - pim * (bb)); }
            CROSS(v1, v0, a10, b10)
            CROSS(v2, v0, a20, b20)
            CROSS(v2, v1, a21, b21)
            CROSS(v3, v0, a30, b30)
            CROSS(v3, v1, a31, b31)
            CROSS(v3, v2, a32, b32)
#undef CROSS
        }
#pragma unroll
        for (int off = 16; off; off >>= 1) acc += __shfl_xor_sync(FULLMASK, acc, off);
        if (lane == 0) part[w * 2 + W] = acc;
    }
    __syncthreads();

    // head: out[b][j] = sum_w e[w] * head_w[j*7+w] + head_b[j]
#pragma unroll
    for (int u = 0; u < 2; ++u) {
        int j = u * 64 + tid;
        float o = head_b[j];
#pragma unroll
        for (int w = 0; w < 7; ++w) o = fmaf(part[w*2] + part[w*2+1], head_w[j * 7 + w], o);
        out[b * 128 + j] = o;
    }
}

// ---------------- fused MLP kernel: 2 batch rows per block ----------------
__device__ __forceinline__ float silu_f(float x) { return x * (1.f / (1.f + expf(-x))); }

__global__ void __launch_bounds__(256) k_mlp(
    const float* __restrict__ t, const float* __restrict__ z_t,
    const float* __restrict__ te_w1, const float* __restrict__ te_b1,
    const float* __restrict__ te_w2, const float* __restrict__ te_b2,
    const float* __restrict__ ip_w1, const float* __restrict__ ip_b1,
    const float* __restrict__ ip_w2, const float* __restrict__ ip_b2) {
    __shared__ float emb[2][128];
    __shared__ float hb[2][128];
    __shared__ float cat[2][256];
    __shared__ float g1[2][256];
    const int tid = threadIdx.x;
    const int r0 = blockIdx.x * 2;

    // stage A: sinusoidal embedding + copy z_t into cat
    {
        int row = tid >> 7, i = tid & 127;
        float tv = t[r0 + row];
        int ii = i & 63;
        float f = expf(-9.2103403719761836f * (float)ii * (1.f / 64.f));
        float a = tv * f;
        emb[row][i] = (i < 64) ? cosf(a) : sinf(a);
        cat[row][i] = z_t[(r0 + row) * 128 + i];
    }
    __syncthreads();

    // stage B: h = silu(te_w1 @ emb + te_b1)
    if (tid < 128) {
        int j = tid;
        float a0 = te_b1[j], a1 = a0;
        const float4* w4 = reinterpret_cast<const float4*>(te_w1 + j * 128);
#pragma unroll 8
        for (int k4 = 0; k4 < 32; ++k4) {
            float4 wv = w4[k4];
            float4 x0 = *reinterpret_cast<const float4*>(&emb[0][k4 * 4]);
            float4 x1 = *reinterpret_cast<const float4*>(&emb[1][k4 * 4]);
            a0 = fmaf(wv.x, x0.x, a0); a0 = fmaf(wv.y, x0.y, a0);
            a0 = fmaf(wv.z, x0.z, a0); a0 = fmaf(wv.w, x0.w, a0);
            a1 = fmaf(wv.x, x1.x, a1); a1 = fmaf(wv.y, x1.y, a1);
            a1 = fmaf(wv.z, x1.z, a1); a1 = fmaf(wv.w, x1.w, a1);
        }
        hb[0][j] = silu_f(a0); hb[1][j] = silu_f(a1);
    }
    __syncthreads();

    // stage C: t_emb2 = te_w2 @ h + te_b2 -> cat[., 128+j]
    if (tid < 128) {
        int j = tid;
        float a0 = te_b2[j], a1 = a0;
        const float4* w4 = reinterpret_cast<const float4*>(te_w2 + j * 128);
#pragma unroll 8
        for (int k4 = 0; k4 < 32; ++k4) {
            float4 wv = w4[k4];
            float4 x0 = *reinterpret_cast<const float4*>(&hb[0][k4 * 4]);
            float4 x1 = *reinterpret_cast<const float4*>(&hb[1][k4 * 4]);
            a0 = fmaf(wv.x, x0.x, a0); a0 = fmaf(wv.y, x0.y, a0);
            a0 = fmaf(wv.z, x0.z, a0); a0 = fmaf(wv.w, x0.w, a0);
            a1 = fmaf(wv.x, x1.x, a1); a1 = fmaf(wv.y, x1.y, a1);
            a1 = fmaf(wv.z, x1.z, a1); a1 = fmaf(wv.w, x1.w, a1);
        }
        cat[0][128 + j] = a0; cat[1][128 + j] = a1;
    }
    __syncthreads();

    // stage D: g1 = silu(ip_w1 @ cat + ip_b1)
    {
        int j = tid;
        float a0 = ip_b1[j], a1 = a0;
        const float4* w4 = reinterpret_cast<const float4*>(ip_w1 + j * 256);
#pragma unroll 8
        for (int k4 = 0; k4 < 64; ++k4) {
            float4 wv = w4[k4];
            float4 x0 = *reinterpret_cast<const float4*>(&cat[0][k4 * 4]);
            float4 x1 = *reinterpret_cast<const float4*>(&cat[1][k4 * 4]);
            a0 = fmaf(wv.x, x0.x, a0); a0 = fmaf(wv.y, x0.y, a0);
            a0 = fmaf(wv.z, x0.z, a0); a0 = fmaf(wv.w, x0.w, a0);
            a1 = fmaf(wv.x, x1.x, a1); a1 = fmaf(wv.y, x1.y, a1);
            a1 = fmaf(wv.z, x1.z, a1); a1 = fmaf(wv.w, x1.w, a1);
        }
        g1[0][j] = silu_f(a0); g1[1][j] = silu_f(a1);
    }
    __syncthreads();

    // stage E: ts = sigmoid(ip_w2 @ g1 + ip_b2) * 2pi
    {
        int j = tid;
        float a0 = ip_b2[j], a1 = a0;
        const float4* w4 = reinterpret_cast<const float4*>(ip_w2 + j * 256);
#pragma unroll 8
        for (int k4 = 0; k4 < 64; ++k4) {
            float4 wv = w4[k4];
            float4 x0 = *reinterpret_cast<const float4*>(&g1[0][k4 * 4]);
            float4 x1 = *reinterpret_cast<const float4*>(&g1[1][k4 * 4]);
            a0 = fmaf(wv.x, x0.x, a0); a0 = fmaf(wv.y, x0.y, a0);
            a0 = fmaf(wv.z, x0.z, a0); a0 = fmaf(wv.w, x0.w, a0);
            a1 = fmaf(wv.x, x1.x, a1); a1 = fmaf(wv.y, x1.y, a1);
            a1 = fmaf(wv.z, x1.z, a1); a1 = fmaf(wv.w, x1.w, a1);
        }
        g_ts[r0 * 256 + j]       = TWO_PI_F / (1.f + expf(-a0));
        g_ts[(r0 + 1) * 256 + j] = TWO_PI_F / (1.f + expf(-a1));
    }
}

// ---------------- launch ----------------
extern "C" void kernel_launch(void* const* d_in, const int* in_sizes, int n_in,
                              void* d_out, int out_size) {
    const float* z_t    = (const float*)d_in[0];
    const float* t      = (const float*)d_in[1];
    const float* te_w1  = (const float*)d_in[2];
    const float* te_b1  = (const float*)d_in[3];
    const float* te_w2  = (const float*)d_in[4];
    const float* te_b2  = (const float*)d_in[5];
    const float* ip_w1  = (const float*)d_in[6];
    const float* ip_b1  = (const float*)d_in[7];
    const float* ip_w2  = (const float*)d_in[8];
    const float* ip_b2  = (const float*)d_in[9];
    const float* prep   = (const float*)d_in[10];
    const float* sig    = (const float*)d_in[11];
    const float* qff    = (const float*)d_in[12];
    const float* A_obs  = (const float*)d_in[13];
    const float* B_obs  = (const float*)d_in[14];
    const float* D_obs  = (const float*)d_in[15];
    const float* head_w = (const float*)d_in[16];
    const float* head_b = (const float*)d_in[17];
    float* out = (float*)d_out;

    k_mlp<<<128, 256>>>(t, z_t, te_w1, te_b1, te_w2, te_b2, ip_w1, ip_b1, ip_w2, ip_b2);
    k_sim<<<256, 64>>>(prep, sig, qff, A_obs, B_obs, D_obs, head_w, head_b, out);
}